// round 3
// baseline (speedup 1.0000x reference)
#include <cuda_runtime.h>
#include <cstdint>

#define DIM   2048
#define NHEAD 16
#define HDIM  128
#define BATCH 2
#define SEQ   2048
#define MROWS (BATCH*SEQ)   // 4096

// Scratch (allocation-free rule: __device__ globals)
__device__ float g_q[(size_t)MROWS * DIM];
__device__ float g_k[(size_t)MROWS * DIM];
__device__ float g_v[(size_t)MROWS * DIM];
__device__ float g_attn[(size_t)MROWS * DIM];

__device__ __forceinline__ uint32_t f2tf32(float x) {
    uint32_t y;
    asm("cvt.rna.tf32.f32 %0, %1;" : "=r"(y) : "f"(x));
    return y;
}
__device__ __forceinline__ float f2tf32f(float x) { return __uint_as_float(f2tf32(x)); }

__device__ __forceinline__ void mma_tf32(float c[4], const uint32_t a[4], const uint32_t b[2]) {
    asm volatile(
        "mma.sync.aligned.m16n8k8.row.col.f32.tf32.tf32.f32 "
        "{%0,%1,%2,%3}, {%4,%5,%6,%7}, {%8,%9}, {%0,%1,%2,%3};\n"
        : "+f"(c[0]), "+f"(c[1]), "+f"(c[2]), "+f"(c[3])
        : "r"(a[0]), "r"(a[1]), "r"(a[2]), "r"(a[3]), "r"(b[0]), "r"(b[1]));
}

// ---------------------------------------------------------------------------
// C[m,n] = sum_k A[m,k] * B[n,k]   (both K-major: "TN" GEMM, y = x @ W^T)
// M=4096, N=K=2048. CTA tile 128x128, BK=32, 256 threads (8 warps, 4x2).
// ---------------------------------------------------------------------------
__global__ __launch_bounds__(256) void gemm_tn_kernel(const float* __restrict__ A,
                                                      const float* __restrict__ B,
                                                      float* __restrict__ C) {
    const int K = DIM, N = DIM;
    __shared__ float As[128][36];
    __shared__ float Bs[128][36];

    const int tid  = threadIdx.x;
    const int m0   = blockIdx.y * 128;
    const int n0   = blockIdx.x * 128;
    const int warp = tid >> 5, lane = tid & 31;
    const int wm   = warp >> 1, wn = warp & 1;   // warp tile 32(M) x 64(N)
    const int r    = lane >> 2, cq = lane & 3;

    float acc[2][8][4];
#pragma unroll
    for (int i = 0; i < 2; i++)
#pragma unroll
        for (int j = 0; j < 8; j++)
#pragma unroll
            for (int q = 0; q < 4; q++) acc[i][j][q] = 0.f;

    const int lr = tid >> 3;        // 0..31
    const int lc = (tid & 7) * 4;   // 0..28

    for (int k0 = 0; k0 < K; k0 += 32) {
#pragma unroll
        for (int i = 0; i < 4; i++) {
            int row = lr + i * 32;
            float4 va = *(const float4*)(A + (size_t)(m0 + row) * K + k0 + lc);
            float4 vb = *(const float4*)(B + (size_t)(n0 + row) * K + k0 + lc);
            *(float4*)&As[row][lc] =
                make_float4(f2tf32f(va.x), f2tf32f(va.y), f2tf32f(va.z), f2tf32f(va.w));
            *(float4*)&Bs[row][lc] =
                make_float4(f2tf32f(vb.x), f2tf32f(vb.y), f2tf32f(vb.z), f2tf32f(vb.w));
        }
        __syncthreads();

#pragma unroll
        for (int kk = 0; kk < 32; kk += 8) {
            uint32_t af[2][4], bf[8][2];
#pragma unroll
            for (int mt = 0; mt < 2; mt++) {
                int base = wm * 32 + mt * 16;
                af[mt][0] = __float_as_uint(As[base + r][kk + cq]);
                af[mt][1] = __float_as_uint(As[base + r + 8][kk + cq]);
                af[mt][2] = __float_as_uint(As[base + r][kk + cq + 4]);
                af[mt][3] = __float_as_uint(As[base + r + 8][kk + cq + 4]);
            }
#pragma unroll
            for (int nt = 0; nt < 8; nt++) {
                int bb = wn * 64 + nt * 8;
                bf[nt][0] = __float_as_uint(Bs[bb + r][kk + cq]);
                bf[nt][1] = __float_as_uint(Bs[bb + r][kk + cq + 4]);
            }
#pragma unroll
            for (int mt = 0; mt < 2; mt++)
#pragma unroll
                for (int nt = 0; nt < 8; nt++) mma_tf32(acc[mt][nt], af[mt], bf[nt]);
        }
        __syncthreads();
    }

#pragma unroll
    for (int mt = 0; mt < 2; mt++) {
        int row0 = m0 + wm * 32 + mt * 16 + r;
#pragma unroll
        for (int nt = 0; nt < 8; nt++) {
            int col = n0 + wn * 64 + nt * 8 + 2 * cq;
            *(float2*)&C[(size_t)row0 * N + col] = make_float2(acc[mt][nt][0], acc[mt][nt][1]);
            *(float2*)&C[(size_t)(row0 + 8) * N + col] = make_float2(acc[mt][nt][2], acc[mt][nt][3]);
        }
    }
}

// ---------------------------------------------------------------------------
// RoPE (non-interleaved / chunk-half), in-place on Q and K.
// One thread per (b, s, h, j) with j in [0,64).
// ---------------------------------------------------------------------------
__global__ void rope_kernel(float* __restrict__ q, float* __restrict__ k) {
    int t = blockIdx.x * blockDim.x + threadIdx.x;
    const int total = BATCH * SEQ * NHEAD * 64;
    if (t >= total) return;
    int j = t & 63;
    int h = (t >> 6) & (NHEAD - 1);
    int s = (t >> 10) & (SEQ - 1);
    int b = t >> 21;
    size_t off = ((size_t)(b * SEQ + s)) * DIM + h * HDIM + j;
    float inv = powf(10000.0f, -(float)(2 * j) * (1.0f / 128.0f));
    float ph = (float)s * inv;
    float sn, cs;
    sincosf(ph, &sn, &cs);
    float q1 = q[off], q2 = q[off + 64];
    q[off]      = q1 * cs - q2 * sn;
    q[off + 64] = q1 * sn + q2 * cs;
    float k1 = k[off], k2 = k[off + 64];
    k[off]      = k1 * cs - k2 * sn;
    k[off + 64] = k1 * sn + k2 * cs;
}

// ---------------------------------------------------------------------------
// Causal flash attention. Grid: (S/64, H, B). 128 threads (4 warps x 16 rows).
// KV blocks of 32 keys. Q cached in registers as tf32 A-fragments.
// ---------------------------------------------------------------------------
__global__ __launch_bounds__(128) void flash_kernel(const float* __restrict__ Q,
                                                    const float* __restrict__ Kg,
                                                    const float* __restrict__ Vg,
                                                    float* __restrict__ O) {
    __shared__ float Ks[32][132];     // [key][d]
    __shared__ float Vt[128][36];     // [d][key]  (transposed V)
    __shared__ float Pw[4][16][36];   // per-warp P staging

    const int tid = threadIdx.x;
    const int warp = tid >> 5, lane = tid & 31;
    const int r = lane >> 2, cq = lane & 3;
    const int q0 = blockIdx.x * 64;
    const int h = blockIdx.y, b = blockIdx.z;
    const size_t head_off = (size_t)b * SEQ * DIM + (size_t)h * HDIM;

    // ---- Q fragments (16 rows per warp, full D=128 => 16 k-chunks) ----
    const float* Qp = Q + head_off + (size_t)(q0 + warp * 16) * DIM;
    uint32_t aQ[16][4];
#pragma unroll
    for (int kc = 0; kc < 16; kc++) {
        aQ[kc][0] = f2tf32(Qp[(size_t)r * DIM + kc * 8 + cq]);
        aQ[kc][1] = f2tf32(Qp[(size_t)(r + 8) * DIM + kc * 8 + cq]);
        aQ[kc][2] = f2tf32(Qp[(size_t)r * DIM + kc * 8 + cq + 4]);
        aQ[kc][3] = f2tf32(Qp[(size_t)(r + 8) * DIM + kc * 8 + cq + 4]);
    }

    float o[16][4];
#pragma unroll
    for (int i = 0; i < 16; i++)
#pragma unroll
        for (int j = 0; j < 4; j++) o[i][j] = 0.f;
    float m0 = -1e30f, m1 = -1e30f, l0 = 0.f, l1 = 0.f;

    const int nkb = (q0 >> 5) + 2;  // causal: keys up to q0+63
    for (int kb = 0; kb < nkb; kb++) {
        const int kstart = kb * 32;
        __syncthreads();

        // K tile -> smem (coalesced float4)
        const float* Kp = Kg + head_off + (size_t)kstart * DIM;
#pragma unroll
        for (int t2 = 0; t2 < 8; t2++) {
            int lin = t2 * 128 + tid;
            int key = lin >> 5;
            int dg = (lin & 31) * 4;
            float4 v = *(const float4*)(Kp + (size_t)key * DIM + dg);
            *(float4*)&Ks[key][dg] =
                make_float4(f2tf32f(v.x), f2tf32f(v.y), f2tf32f(v.z), f2tf32f(v.w));
        }
        // V tile -> smem transposed (conflict-free smem stores)
        const float* Vp = Vg + head_off + (size_t)kstart * DIM;
        const int vkey = tid & 31;
#pragma unroll
        for (int t2 = 0; t2 < 8; t2++) {
            int dg = ((tid >> 5) * 8 + t2) * 4;
            float4 v = *(const float4*)(Vp + (size_t)vkey * DIM + dg);
            Vt[dg + 0][vkey] = f2tf32f(v.x);
            Vt[dg + 1][vkey] = f2tf32f(v.y);
            Vt[dg + 2][vkey] = f2tf32f(v.z);
            Vt[dg + 3][vkey] = f2tf32f(v.w);
        }
        __syncthreads();

        // ---- scores S = Q @ K^T (16x32 per warp) ----
        float s[4][4];
#pragma unroll
        for (int nt = 0; nt < 4; nt++)
#pragma unroll
            for (int j = 0; j < 4; j++) s[nt][j] = 0.f;
#pragma unroll
        for (int kc = 0; kc < 16; kc++) {
#pragma unroll
            for (int nt = 0; nt < 4; nt++) {
                uint32_t bf[2];
                bf[0] = __float_as_uint(Ks[nt * 8 + r][kc * 8 + cq]);
                bf[1] = __float_as_uint(Ks[nt * 8 + r][kc * 8 + cq + 4]);
                mma_tf32(s[nt], aQ[kc], bf);
            }
        }

        const float scale = 0.08838834764831843f;  // 1/sqrt(128)
        const int qrow0 = q0 + warp * 16 + r;
        const bool need_mask = (kstart + 31 > q0 + warp * 16);
#pragma unroll
        for (int nt = 0; nt < 4; nt++) {
#pragma unroll
            for (int u = 0; u < 2; u++) {
                int key = kstart + nt * 8 + 2 * cq + u;
                s[nt][u] *= scale;
                s[nt][2 + u] *= scale;
                if (need_mask) {
                    if (key > qrow0) s[nt][u] = -1e30f;
                    if (key > qrow0 + 8) s[nt][2 + u] = -1e30f;
                }
            }
        }

        // ---- online softmax ----
        float mx0 = -1e30f, mx1 = -1e30f;
#pragma unroll
        for (int nt = 0; nt < 4; nt++) {
            mx0 = fmaxf(mx0, fmaxf(s[nt][0], s[nt][1]));
            mx1 = fmaxf(mx1, fmaxf(s[nt][2], s[nt][3]));
        }
        mx0 = fmaxf(mx0, __shfl_xor_sync(0xffffffffu, mx0, 1));
        mx0 = fmaxf(mx0, __shfl_xor_sync(0xffffffffu, mx0, 2));
        mx1 = fmaxf(mx1, __shfl_xor_sync(0xffffffffu, mx1, 1));
        mx1 = fmaxf(mx1, __shfl_xor_sync(0xffffffffu, mx1, 2));
        float mn0 = fmaxf(m0, mx0), mn1 = fmaxf(m1, mx1);
        float al0 = __expf(m0 - mn0), al1 = __expf(m1 - mn1);
        float sum0 = 0.f, sum1 = 0.f;
#pragma unroll
        for (int nt = 0; nt < 4; nt++) {
            s[nt][0] = __expf(s[nt][0] - mn0);
            s[nt][1] = __expf(s[nt][1] - mn0);
            s[nt][2] = __expf(s[nt][2] - mn1);
            s[nt][3] = __expf(s[nt][3] - mn1);
            sum0 += s[nt][0] + s[nt][1];
            sum1 += s[nt][2] + s[nt][3];
        }
        sum0 += __shfl_xor_sync(0xffffffffu, sum0, 1);
        sum0 += __shfl_xor_sync(0xffffffffu, sum0, 2);
        sum1 += __shfl_xor_sync(0xffffffffu, sum1, 1);
        sum1 += __shfl_xor_sync(0xffffffffu, sum1, 2);
        l0 = l0 * al0 + sum0;
        l1 = l1 * al1 + sum1;
        m0 = mn0;
        m1 = mn1;
#pragma unroll
        for (int nt = 0; nt < 16; nt++) {
            o[nt][0] *= al0;
            o[nt][1] *= al0;
            o[nt][2] *= al1;
            o[nt][3] *= al1;
        }

        // stage P through smem to form A-fragments
#pragma unroll
        for (int nt = 0; nt < 4; nt++) {
            Pw[warp][r][nt * 8 + 2 * cq] = f2tf32f(s[nt][0]);
            Pw[warp][r][nt * 8 + 2 * cq + 1] = f2tf32f(s[nt][1]);
            Pw[warp][r + 8][nt * 8 + 2 * cq] = f2tf32f(s[nt][2]);
            Pw[warp][r + 8][nt * 8 + 2 * cq + 1] = f2tf32f(s[nt][3]);
        }
        __syncwarp();

        // ---- O += P @ V ----
#pragma unroll
        for (int kc2 = 0; kc2 < 4; kc2++) {
            uint32_t aP[4];
            aP[0] = __float_as_uint(Pw[warp][r][kc2 * 8 + cq]);
            aP[1] = __float_as_uint(Pw[warp][r + 8][kc2 * 8 + cq]);
            aP[2] = __float_as_uint(Pw[warp][r][kc2 * 8 + cq + 4]);
            aP[3] = __float_as_uint(Pw[warp][r + 8][kc2 * 8 + cq + 4]);
#pragma unroll
            for (int nt = 0; nt < 16; nt++) {
                uint32_t bv[2];
                bv[0] = __float_as_uint(Vt[nt * 8 + r][kc2 * 8 + cq]);
                bv[1] = __float_as_uint(Vt[nt * 8 + r][kc2 * 8 + cq + 4]);
                mma_tf32(o[nt], aP, bv);
            }
        }
    }

    const float inv0 = 1.f / l0, inv1 = 1.f / l1;
    float* Op = O + head_off + (size_t)(q0 + warp * 16) * DIM;
#pragma unroll
    for (int nt = 0; nt < 16; nt++) {
        int col = nt * 8 + 2 * cq;
        *(float2*)&Op[(size_t)r * DIM + col] = make_float2(o[nt][0] * inv0, o[nt][1] * inv0);
        *(float2*)&Op[(size_t)(r + 8) * DIM + col] = make_float2(o[nt][2] * inv1, o[nt][3] * inv1);
    }
}

// ---------------------------------------------------------------------------
extern "C" void kernel_launch(void* const* d_in, const int* in_sizes, int n_in,
                              void* d_out, int out_size) {
    const float* x  = (const float*)d_in[0];
    const float* Wq = (const float*)d_in[1];
    const float* Wk = (const float*)d_in[2];
    const float* Wv = (const float*)d_in[3];
    const float* Wo = (const float*)d_in[4];
    float* out = (float*)d_out;

    float *qp, *kp, *vp, *ap;
    cudaGetSymbolAddress((void**)&qp, g_q);
    cudaGetSymbolAddress((void**)&kp, g_k);
    cudaGetSymbolAddress((void**)&vp, g_v);
    cudaGetSymbolAddress((void**)&ap, g_attn);

    dim3 gg(DIM / 128, MROWS / 128);  // (16, 32)
    gemm_tn_kernel<<<gg, 256>>>(x, Wq, qp);
    gemm_tn_kernel<<<gg, 256>>>(x, Wk, kp);
    gemm_tn_kernel<<<gg, 256>>>(x, Wv, vp);

    const int rope_threads = BATCH * SEQ * NHEAD * 64;
    rope_kernel<<<rope_threads / 256, 256>>>(qp, kp);

    flash_kernel<<<dim3(SEQ / 64, NHEAD, BATCH), 128>>>(qp, kp, vp, ap);

    gemm_tn_kernel<<<gg, 256>>>(ap, Wo, out);
}

// round 5
// speedup vs baseline: 1.1154x; 1.1154x over previous
#include <cuda_runtime.h>
#include <cstdint>

#define DIM   2048
#define NHEAD 16
#define HDIM  128
#define BATCH 2
#define SEQ   2048
#define MROWS (BATCH*SEQ)   // 4096

#define BM 128
#define BN 128
#define BK 32
#define STAGES 3
#define ROWF 36                       // padded row stride in floats (144B, 16B-aligned, conflict-free)
#define STAGE_ELEMS (128 * ROWF)
#define SMEM_BYTES (STAGES * 2 * STAGE_ELEMS * 4)   // 110592

// Scratch (allocation-free rule: __device__ globals)
__device__ float g_q[(size_t)MROWS * DIM];
__device__ float g_k[(size_t)MROWS * DIM];
__device__ float g_v[(size_t)MROWS * DIM];
__device__ float g_attn[(size_t)MROWS * DIM];
__device__ float g_xr[(size_t)MROWS * DIM];      // tf32-rounded x
__device__ float g_wqr[(size_t)DIM * DIM];
__device__ float g_wkr[(size_t)DIM * DIM];
__device__ float g_wvr[(size_t)DIM * DIM];
__device__ float g_wor[(size_t)DIM * DIM];

__device__ __forceinline__ uint32_t f2tf32(float x) {
    uint32_t y;
    asm("cvt.rna.tf32.f32 %0, %1;" : "=r"(y) : "f"(x));
    return y;
}
__device__ __forceinline__ float f2tf32f(float x) { return __uint_as_float(f2tf32(x)); }

__device__ __forceinline__ void mma_tf32(float c[4], const uint32_t a[4], const uint32_t b[2]) {
    asm volatile(
        "mma.sync.aligned.m16n8k8.row.col.f32.tf32.tf32.f32 "
        "{%0,%1,%2,%3}, {%4,%5,%6,%7}, {%8,%9}, {%0,%1,%2,%3};\n"
        : "+f"(c[0]), "+f"(c[1]), "+f"(c[2]), "+f"(c[3])
        : "r"(a[0]), "r"(a[1]), "r"(a[2]), "r"(a[3]), "r"(b[0]), "r"(b[1]));
}

__device__ __forceinline__ void cp16(float* dst, const float* src) {
    uint32_t s = (uint32_t)__cvta_generic_to_shared(dst);
    asm volatile("cp.async.cg.shared.global [%0], [%1], 16;" :: "r"(s), "l"(src));
}

// ---------------------------------------------------------------------------
// Elementwise tf32 rounding pass (float4 vectorized)
// ---------------------------------------------------------------------------
__global__ void round_tf32_kernel(const float* __restrict__ in, float* __restrict__ out, int n4) {
    int t = blockIdx.x * blockDim.x + threadIdx.x;
    if (t >= n4) return;
    float4 v = ((const float4*)in)[t];
    ((float4*)out)[t] = make_float4(f2tf32f(v.x), f2tf32f(v.y), f2tf32f(v.z), f2tf32f(v.w));
}

// ---------------------------------------------------------------------------
// Pipelined TN GEMM: C[m,n] = sum_k A[m,k] * B[n,k]. Inputs pre-rounded to tf32.
// CTA tile 128x128, BK=32, 4 warps (warp tile 64x64), 3-stage cp.async.
// ---------------------------------------------------------------------------
__device__ __forceinline__ void gemm_body(const float* __restrict__ A,
                                          const float* __restrict__ B,
                                          float* __restrict__ C,
                                          float* smem) {
    const int K = DIM, N = DIM;
    const int tid  = threadIdx.x;
    const int m0   = blockIdx.y * BM;
    const int n0   = blockIdx.x * BN;
    const int warp = tid >> 5, lane = tid & 31;
    const int wm   = warp >> 1, wn = warp & 1;   // 2x2 warps, warp tile 64x64
    const int r    = lane >> 2, cq = lane & 3;

    float* As = smem;
    float* Bs = smem + STAGES * STAGE_ELEMS;

    float acc[4][8][4];
#pragma unroll
    for (int mt = 0; mt < 4; mt++)
#pragma unroll
        for (int nt = 0; nt < 8; nt++)
#pragma unroll
            for (int q = 0; q < 4; q++) acc[mt][nt][q] = 0.f;

    const int lrow = tid >> 3;       // 0..15
    const int lcol = (tid & 7) * 4;  // 0..28

#define LOAD_STAGE(slot, kt)                                                     \
    do {                                                                         \
        const float* Ag = A + (size_t)m0 * K + (kt) * BK;                        \
        const float* Bg = B + (size_t)n0 * K + (kt) * BK;                        \
        float* as = As + (slot) * STAGE_ELEMS;                                   \
        float* bs = Bs + (slot) * STAGE_ELEMS;                                   \
        _Pragma("unroll")                                                        \
        for (int i = 0; i < 8; i++) {                                            \
            int row = lrow + i * 16;                                             \
            cp16(as + row * ROWF + lcol, Ag + (size_t)row * K + lcol);           \
            cp16(bs + row * ROWF + lcol, Bg + (size_t)row * K + lcol);           \
        }                                                                        \
    } while (0)

#pragma unroll
    for (int s = 0; s < STAGES - 1; s++) {
        LOAD_STAGE(s, s);
        asm volatile("cp.async.commit_group;");
    }

    const int KT = K / BK;  // 64
    for (int kt = 0; kt < KT; kt++) {
        asm volatile("cp.async.wait_group 1;");
        __syncthreads();
        int pf = kt + STAGES - 1;
        if (pf < KT) LOAD_STAGE(pf % STAGES, pf);
        asm volatile("cp.async.commit_group;");

        const float* as = As + (kt % STAGES) * STAGE_ELEMS;
        const float* bs = Bs + (kt % STAGES) * STAGE_ELEMS;
#pragma unroll
        for (int kk = 0; kk < BK; kk += 8) {
            uint32_t af[4][4], bf[8][2];
#pragma unroll
            for (int mt = 0; mt < 4; mt++) {
                const float* ap = as + (wm * 64 + mt * 16) * ROWF + kk;
                af[mt][0] = __float_as_uint(ap[(size_t)r * ROWF + cq]);
                af[mt][1] = __float_as_uint(ap[(size_t)(r + 8) * ROWF + cq]);
                af[mt][2] = __float_as_uint(ap[(size_t)r * ROWF + cq + 4]);
                af[mt][3] = __float_as_uint(ap[(size_t)(r + 8) * ROWF + cq + 4]);
            }
#pragma unroll
            for (int nt = 0; nt < 8; nt++) {
                const float* bp = bs + (wn * 64 + nt * 8 + r) * ROWF + kk;
                bf[nt][0] = __float_as_uint(bp[cq]);
                bf[nt][1] = __float_as_uint(bp[cq + 4]);
            }
#pragma unroll
            for (int mt = 0; mt < 4; mt++)
#pragma unroll
                for (int nt = 0; nt < 8; nt++) mma_tf32(acc[mt][nt], af[mt], bf[nt]);
        }
    }
#undef LOAD_STAGE

#pragma unroll
    for (int mt = 0; mt < 4; mt++) {
        int row0 = m0 + wm * 64 + mt * 16 + r;
#pragma unroll
        for (int nt = 0; nt < 8; nt++) {
            int col = n0 + wn * 64 + nt * 8 + 2 * cq;
            *(float2*)&C[(size_t)row0 * N + col] = make_float2(acc[mt][nt][0], acc[mt][nt][1]);
            *(float2*)&C[(size_t)(row0 + 8) * N + col] = make_float2(acc[mt][nt][2], acc[mt][nt][3]);
        }
    }
}

__global__ __launch_bounds__(128, 2) void gemm_qkv_kernel(
    const float* __restrict__ x,
    const float* __restrict__ wq, const float* __restrict__ wk, const float* __restrict__ wv,
    float* __restrict__ q, float* __restrict__ k, float* __restrict__ v) {
    extern __shared__ float smem[];
    const float* B = (blockIdx.z == 0) ? wq : (blockIdx.z == 1) ? wk : wv;
    float* C       = (blockIdx.z == 0) ? q  : (blockIdx.z == 1) ? k  : v;
    gemm_body(x, B, C, smem);
}

__global__ __launch_bounds__(128, 2) void gemm_single_kernel(const float* __restrict__ A,
                                                             const float* __restrict__ B,
                                                             float* __restrict__ C) {
    extern __shared__ float smem[];
    gemm_body(A, B, C, smem);
}

// ---------------------------------------------------------------------------
// RoPE (non-interleaved / chunk-half), in-place on Q and K.
// ---------------------------------------------------------------------------
__global__ void rope_kernel(float* __restrict__ q, float* __restrict__ k) {
    int t = blockIdx.x * blockDim.x + threadIdx.x;
    const int total = BATCH * SEQ * NHEAD * 64;
    if (t >= total) return;
    int j = t & 63;
    int h = (t >> 6) & (NHEAD - 1);
    int s = (t >> 10) & (SEQ - 1);
    int b = t >> 21;
    size_t off = ((size_t)(b * SEQ + s)) * DIM + h * HDIM + j;
    float inv = powf(10000.0f, -(float)(2 * j) * (1.0f / 128.0f));
    float ph = (float)s * inv;
    float sn, cs;
    sincosf(ph, &sn, &cs);
    float q1 = q[off], q2 = q[off + 64];
    q[off]      = q1 * cs - q2 * sn;
    q[off + 64] = q1 * sn + q2 * cs;
    float k1 = k[off], k2 = k[off + 64];
    k[off]      = k1 * cs - k2 * sn;
    k[off + 64] = k1 * sn + k2 * cs;
}

// ---------------------------------------------------------------------------
// Causal flash attention. Grid: (S/64, H, B). 128 threads (4 warps x 16 rows).
// KV blocks of 32 keys. Q cached in registers as tf32 A-fragments.
// Epilogue writes tf32-rounded output (feeds the pre-rounded O-proj GEMM).
// ---------------------------------------------------------------------------
__global__ __launch_bounds__(128) void flash_kernel(const float* __restrict__ Q,
                                                    const float* __restrict__ Kg,
                                                    const float* __restrict__ Vg,
                                                    float* __restrict__ O) {
    __shared__ float Ks[32][132];     // [key][d]
    __shared__ float Vt[128][36];     // [d][key]  (transposed V)
    __shared__ float Pw[4][16][36];   // per-warp P staging

    const int tid = threadIdx.x;
    const int warp = tid >> 5, lane = tid & 31;
    const int r = lane >> 2, cq = lane & 3;
    const int q0 = blockIdx.x * 64;
    const int h = blockIdx.y, b = blockIdx.z;
    const size_t head_off = (size_t)b * SEQ * DIM + (size_t)h * HDIM;

    const float* Qp = Q + head_off + (size_t)(q0 + warp * 16) * DIM;
    uint32_t aQ[16][4];
#pragma unroll
    for (int kc = 0; kc < 16; kc++) {
        aQ[kc][0] = f2tf32(Qp[(size_t)r * DIM + kc * 8 + cq]);
        aQ[kc][1] = f2tf32(Qp[(size_t)(r + 8) * DIM + kc * 8 + cq]);
        aQ[kc][2] = f2tf32(Qp[(size_t)r * DIM + kc * 8 + cq + 4]);
        aQ[kc][3] = f2tf32(Qp[(size_t)(r + 8) * DIM + kc * 8 + cq + 4]);
    }

    float o[16][4];
#pragma unroll
    for (int i = 0; i < 16; i++)
#pragma unroll
        for (int j = 0; j < 4; j++) o[i][j] = 0.f;
    float m0 = -1e30f, m1 = -1e30f, l0 = 0.f, l1 = 0.f;

    const int nkb = (q0 >> 5) + 2;  // causal: keys up to q0+63
    for (int kb = 0; kb < nkb; kb++) {
        const int kstart = kb * 32;
        __syncthreads();

        const float* Kp = Kg + head_off + (size_t)kstart * DIM;
#pragma unroll
        for (int t2 = 0; t2 < 8; t2++) {
            int lin = t2 * 128 + tid;
            int key = lin >> 5;
            int dg = (lin & 31) * 4;
            float4 v = *(const float4*)(Kp + (size_t)key * DIM + dg);
            *(float4*)&Ks[key][dg] =
                make_float4(f2tf32f(v.x), f2tf32f(v.y), f2tf32f(v.z), f2tf32f(v.w));
        }
        const float* Vp = Vg + head_off + (size_t)kstart * DIM;
        const int vkey = tid & 31;
#pragma unroll
        for (int t2 = 0; t2 < 8; t2++) {
            int dg = ((tid >> 5) * 8 + t2) * 4;
            float4 v = *(const float4*)(Vp + (size_t)vkey * DIM + dg);
            Vt[dg + 0][vkey] = f2tf32f(v.x);
            Vt[dg + 1][vkey] = f2tf32f(v.y);
            Vt[dg + 2][vkey] = f2tf32f(v.z);
            Vt[dg + 3][vkey] = f2tf32f(v.w);
        }
        __syncthreads();

        float s[4][4];
#pragma unroll
        for (int nt = 0; nt < 4; nt++)
#pragma unroll
            for (int j = 0; j < 4; j++) s[nt][j] = 0.f;
#pragma unroll
        for (int kc = 0; kc < 16; kc++) {
#pragma unroll
            for (int nt = 0; nt < 4; nt++) {
                uint32_t bf[2];
                bf[0] = __float_as_uint(Ks[nt * 8 + r][kc * 8 + cq]);
                bf[1] = __float_as_uint(Ks[nt * 8 + r][kc * 8 + cq + 4]);
                mma_tf32(s[nt], aQ[kc], bf);
            }
        }

        const float scale = 0.08838834764831843f;  // 1/sqrt(128)
        const int qrow0 = q0 + warp * 16 + r;
        const bool need_mask = (kstart + 31 > q0 + warp * 16);
#pragma unroll
        for (int nt = 0; nt < 4; nt++) {
#pragma unroll
            for (int u = 0; u < 2; u++) {
                int key = kstart + nt * 8 + 2 * cq + u;
                s[nt][u] *= scale;
                s[nt][2 + u] *= scale;
                if (need_mask) {
                    if (key > qrow0) s[nt][u] = -1e30f;
                    if (key > qrow0 + 8) s[nt][2 + u] = -1e30f;
                }
            }
        }

        float mx0 = -1e30f, mx1 = -1e30f;
#pragma unroll
        for (int nt = 0; nt < 4; nt++) {
            mx0 = fmaxf(mx0, fmaxf(s[nt][0], s[nt][1]));
            mx1 = fmaxf(mx1, fmaxf(s[nt][2], s[nt][3]));
        }
        mx0 = fmaxf(mx0, __shfl_xor_sync(0xffffffffu, mx0, 1));
        mx0 = fmaxf(mx0, __shfl_xor_sync(0xffffffffu, mx0, 2));
        mx1 = fmaxf(mx1, __shfl_xor_sync(0xffffffffu, mx1, 1));
        mx1 = fmaxf(mx1, __shfl_xor_sync(0xffffffffu, mx1, 2));
        float mn0 = fmaxf(m0, mx0), mn1 = fmaxf(m1, mx1);
        float al0 = __expf(m0 - mn0), al1 = __expf(m1 - mn1);
        float sum0 = 0.f, sum1 = 0.f;
#pragma unroll
        for (int nt = 0; nt < 4; nt++) {
            s[nt][0] = __expf(s[nt][0] - mn0);
            s[nt][1] = __expf(s[nt][1] - mn0);
            s[nt][2] = __expf(s[nt][2] - mn1);
            s[nt][3] = __expf(s[nt][3] - mn1);
            sum0 += s[nt][0] + s[nt][1];
            sum1 += s[nt][2] + s[nt][3];
        }
        sum0 += __shfl_xor_sync(0xffffffffu, sum0, 1);
        sum0 += __shfl_xor_sync(0xffffffffu, sum0, 2);
        sum1 += __shfl_xor_sync(0xffffffffu, sum1, 1);
        sum1 += __shfl_xor_sync(0xffffffffu, sum1, 2);
        l0 = l0 * al0 + sum0;
        l1 = l1 * al1 + sum1;
        m0 = mn0;
        m1 = mn1;
#pragma unroll
        for (int nt = 0; nt < 16; nt++) {
            o[nt][0] *= al0;
            o[nt][1] *= al0;
            o[nt][2] *= al1;
            o[nt][3] *= al1;
        }

#pragma unroll
        for (int nt = 0; nt < 4; nt++) {
            Pw[warp][r][nt * 8 + 2 * cq] = f2tf32f(s[nt][0]);
            Pw[warp][r][nt * 8 + 2 * cq + 1] = f2tf32f(s[nt][1]);
            Pw[warp][r + 8][nt * 8 + 2 * cq] = f2tf32f(s[nt][2]);
            Pw[warp][r + 8][nt * 8 + 2 * cq + 1] = f2tf32f(s[nt][3]);
        }
        __syncwarp();

#pragma unroll
        for (int kc2 = 0; kc2 < 4; kc2++) {
            uint32_t aP[4];
            aP[0] = __float_as_uint(Pw[warp][r][kc2 * 8 + cq]);
            aP[1] = __float_as_uint(Pw[warp][r + 8][kc2 * 8 + cq]);
            aP[2] = __float_as_uint(Pw[warp][r][kc2 * 8 + cq + 4]);
            aP[3] = __float_as_uint(Pw[warp][r + 8][kc2 * 8 + cq + 4]);
#pragma unroll
            for (int nt = 0; nt < 16; nt++) {
                uint32_t bv[2];
                bv[0] = __float_as_uint(Vt[nt * 8 + r][kc2 * 8 + cq]);
                bv[1] = __float_as_uint(Vt[nt * 8 + r][kc2 * 8 + cq + 4]);
                mma_tf32(o[nt], aP, bv);
            }
        }
    }

    const float inv0 = 1.f / l0, inv1 = 1.f / l1;
    float* Op = O + head_off + (size_t)(q0 + warp * 16) * DIM;
#pragma unroll
    for (int nt = 0; nt < 16; nt++) {
        int col = nt * 8 + 2 * cq;
        *(float2*)&Op[(size_t)r * DIM + col] =
            make_float2(f2tf32f(o[nt][0] * inv0), f2tf32f(o[nt][1] * inv0));
        *(float2*)&Op[(size_t)(r + 8) * DIM + col] =
            make_float2(f2tf32f(o[nt][2] * inv1), f2tf32f(o[nt][3] * inv1));
    }
}

// ---------------------------------------------------------------------------
extern "C" void kernel_launch(void* const* d_in, const int* in_sizes, int n_in,
                              void* d_out, int out_size) {
    const float* x  = (const float*)d_in[0];
    const float* Wq = (const float*)d_in[1];
    const float* Wk = (const float*)d_in[2];
    const float* Wv = (const float*)d_in[3];
    const float* Wo = (const float*)d_in[4];
    float* out = (float*)d_out;

    float *qp, *kp, *vp, *ap, *xr, *wqr, *wkr, *wvr, *wor;
    cudaGetSymbolAddress((void**)&qp, g_q);
    cudaGetSymbolAddress((void**)&kp, g_k);
    cudaGetSymbolAddress((void**)&vp, g_v);
    cudaGetSymbolAddress((void**)&ap, g_attn);
    cudaGetSymbolAddress((void**)&xr, g_xr);
    cudaGetSymbolAddress((void**)&wqr, g_wqr);
    cudaGetSymbolAddress((void**)&wkr, g_wkr);
    cudaGetSymbolAddress((void**)&wvr, g_wvr);
    cudaGetSymbolAddress((void**)&wor, g_wor);

    cudaFuncSetAttribute(gemm_qkv_kernel, cudaFuncAttributeMaxDynamicSharedMemorySize, SMEM_BYTES);
    cudaFuncSetAttribute(gemm_single_kernel, cudaFuncAttributeMaxDynamicSharedMemorySize, SMEM_BYTES);

    const int nx4 = MROWS * DIM / 4;     // 2097152
    const int nw4 = DIM * DIM / 4;       // 1048576
    round_tf32_kernel<<<(nx4 + 255) / 256, 256>>>(x, xr, nx4);
    round_tf32_kernel<<<(nw4 + 255) / 256, 256>>>(Wq, wqr, nw4);
    round_tf32_kernel<<<(nw4 + 255) / 256, 256>>>(Wk, wkr, nw4);
    round_tf32_kernel<<<(nw4 + 255) / 256, 256>>>(Wv, wvr, nw4);
    round_tf32_kernel<<<(nw4 + 255) / 256, 256>>>(Wo, wor, nw4);

    dim3 gqkv(DIM / BN, MROWS / BM, 3);  // (16, 32, 3)
    gemm_qkv_kernel<<<gqkv, 128, SMEM_BYTES>>>(xr, wqr, wkr, wvr, qp, kp, vp);

    const int rope_threads = BATCH * SEQ * NHEAD * 64;
    rope_kernel<<<rope_threads / 256, 256>>>(qp, kp);

    flash_kernel<<<dim3(SEQ / 64, NHEAD, BATCH), 128>>>(qp, kp, vp, ap);

    gemm_single_kernel<<<dim3(DIM / BN, MROWS / BM), 128, SMEM_BYTES>>>(ap, wor, out);
}

// round 7
// speedup vs baseline: 2.9335x; 2.6299x over previous
#include <cuda_runtime.h>
#include <cuda_fp16.h>
#include <cstdint>

#define DIM   2048
#define NHEAD 16
#define HDIM  128
#define BATCH 2
#define SEQ   2048
#define MROWS (BATCH*SEQ)   // 4096

// ---- fp16 GEMM tile config ----
#define GBM 128
#define GBN 128
#define GBK 64                         // 64 halfs = 128 bytes = one swizzle row
#define GSTAGES 3
#define STAGE_T_BYTES (128 * 128)      // one operand tile per stage: 16384 B
#define GSMEM_BYTES (GSTAGES * 2 * STAGE_T_BYTES)   // 98304
#define GTHREADS 256

#define SW128(o) ((o) ^ ((((uint32_t)(o)) >> 3) & 0x70u))

// Scratch (allocation-free rule: __device__ globals)
__device__ __half g_q[(size_t)MROWS * DIM];
__device__ __half g_k[(size_t)MROWS * DIM];
__device__ __half g_v[(size_t)MROWS * DIM];
__device__ __half g_attn[(size_t)MROWS * DIM];
__device__ __half g_xr[(size_t)MROWS * DIM];
__device__ __half g_wqr[(size_t)DIM * DIM];
__device__ __half g_wkr[(size_t)DIM * DIM];
__device__ __half g_wvr[(size_t)DIM * DIM];
__device__ __half g_wor[(size_t)DIM * DIM];

// ---------------------------------------------------------------------------
// PTX helpers
// ---------------------------------------------------------------------------
__device__ __forceinline__ void mma_f16(float c[4], const uint32_t a[4], const uint32_t b[2]) {
    asm volatile(
        "mma.sync.aligned.m16n8k16.row.col.f32.f16.f16.f32 "
        "{%0,%1,%2,%3}, {%4,%5,%6,%7}, {%8,%9}, {%0,%1,%2,%3};\n"
        : "+f"(c[0]), "+f"(c[1]), "+f"(c[2]), "+f"(c[3])
        : "r"(a[0]), "r"(a[1]), "r"(a[2]), "r"(a[3]), "r"(b[0]), "r"(b[1]));
}

#define LDSM_X4(r0, r1, r2, r3, addr)                                       \
    asm volatile("ldmatrix.sync.aligned.m8n8.x4.shared.b16 {%0,%1,%2,%3}, [%4];" \
                 : "=r"(r0), "=r"(r1), "=r"(r2), "=r"(r3) : "r"(addr))

#define LDSM_X4_T(r0, r1, r2, r3, addr)                                     \
    asm volatile("ldmatrix.sync.aligned.m8n8.x4.trans.shared.b16 {%0,%1,%2,%3}, [%4];" \
                 : "=r"(r0), "=r"(r1), "=r"(r2), "=r"(r3) : "r"(addr))

__device__ __forceinline__ void cp16(void* dst, const void* src) {
    uint32_t s = (uint32_t)__cvta_generic_to_shared(dst);
    asm volatile("cp.async.cg.shared.global [%0], [%1], 16;" :: "r"(s), "l"(src));
}

__device__ __forceinline__ uint32_t smem_u32(const void* p) {
    return (uint32_t)__cvta_generic_to_shared(p);
}

__device__ __forceinline__ uint32_t packh2(float a, float b) {
    __half2 h = __floats2half2_rn(a, b);
    return *(uint32_t*)&h;
}

__device__ __forceinline__ void store_pair(__half* p, float a, float b) {
    *(uint32_t*)p = packh2(a, b);
}
__device__ __forceinline__ void store_pair(float* p, float a, float b) {
    *(float2*)p = make_float2(a, b);
}

// ---------------------------------------------------------------------------
// f32 -> f16 conversion pass (rounding point identical role to old tf32 round)
// ---------------------------------------------------------------------------
__global__ void f32_to_f16_kernel(const float* __restrict__ in, __half* __restrict__ out, int n4) {
    int t = blockIdx.x * blockDim.x + threadIdx.x;
    if (t >= n4) return;
    float4 v = ((const float4*)in)[t];
    ((uint2*)out)[t] = make_uint2(packh2(v.x, v.y), packh2(v.z, v.w));
}

// ---------------------------------------------------------------------------
// fp16 TN GEMM: C[m,n] = sum_k A[m,k]*B[n,k], f32 accumulate.
// CTA 128x128, BK=64 halfs, 8 warps (warp tile 64x32), 3-stage cp.async,
// SW128-swizzled smem, ldmatrix fragment loads.
// ---------------------------------------------------------------------------
template <typename OutT>
__device__ __forceinline__ void gemm_fp16_body(const __half* __restrict__ A,
                                               const __half* __restrict__ B,
                                               OutT* __restrict__ C,
                                               char* smem) {
    const int K = DIM, N = DIM;
    const int tid = threadIdx.x;
    const int warp = tid >> 5, lane = tid & 31;
    const int m0 = blockIdx.y * GBM, n0 = blockIdx.x * GBN;
    const int wm = warp >> 2, wn = warp & 3;      // 2x4 warps -> warp tile 64x32
    const int r = lane >> 2, cq = lane & 3;

    char* As = smem;
    char* Bs = smem + GSTAGES * STAGE_T_BYTES;
    const uint32_t uA = smem_u32(As);
    const uint32_t uB = smem_u32(Bs);

    float acc[4][4][4];
#pragma unroll
    for (int mt = 0; mt < 4; mt++)
#pragma unroll
        for (int nf = 0; nf < 4; nf++)
#pragma unroll
            for (int q = 0; q < 4; q++) acc[mt][nf][q] = 0.f;

#define G_LOAD_STAGE(slot, kt)                                                     \
    do {                                                                           \
        const __half* Ag = A + (size_t)m0 * K + (size_t)(kt) * GBK;                \
        const __half* Bg = B + (size_t)n0 * K + (size_t)(kt) * GBK;                \
        _Pragma("unroll")                                                          \
        for (int i = 0; i < 4; i++) {                                              \
            int c = tid + i * GTHREADS;                                            \
            int row = c >> 3, ch = c & 7;                                          \
            uint32_t sw = SW128((uint32_t)(row * 128 + ch * 16));                  \
            cp16(As + (slot) * STAGE_T_BYTES + sw, Ag + (size_t)row * K + ch * 8); \
            cp16(Bs + (slot) * STAGE_T_BYTES + sw, Bg + (size_t)row * K + ch * 8); \
        }                                                                          \
    } while (0)

    G_LOAD_STAGE(0, 0);
    asm volatile("cp.async.commit_group;");
    G_LOAD_STAGE(1, 1);
    asm volatile("cp.async.commit_group;");

    const int KT = K / GBK;  // 32
    for (int kt = 0; kt < KT; kt++) {
        asm volatile("cp.async.wait_group 1;");
        __syncthreads();
        int pf = kt + GSTAGES - 1;
        if (pf < KT) G_LOAD_STAGE(pf % GSTAGES, pf);
        asm volatile("cp.async.commit_group;");

        const uint32_t aBase = uA + (kt % GSTAGES) * STAGE_T_BYTES;
        const uint32_t bBase = uB + (kt % GSTAGES) * STAGE_T_BYTES;

#pragma unroll
        for (int kk = 0; kk < 4; kk++) {          // 4 x k16 per stage
            const int c0 = kk * 2;
            uint32_t af[4][4], bf[4][2];
#pragma unroll
            for (int mt = 0; mt < 4; mt++) {
                int row = wm * 64 + mt * 16 + (lane & 15);
                int ch = c0 + (lane >> 4);
                uint32_t addr = aBase + SW128((uint32_t)(row * 128 + ch * 16));
                LDSM_X4(af[mt][0], af[mt][1], af[mt][2], af[mt][3], addr);
            }
#pragma unroll
            for (int g = 0; g < 2; g++) {
                int row = wn * 32 + g * 16 + (lane & 7) + ((lane >> 4) << 3);
                int ch = c0 + ((lane >> 3) & 1);
                uint32_t addr = bBase + SW128((uint32_t)(row * 128 + ch * 16));
                LDSM_X4(bf[2 * g][0], bf[2 * g][1], bf[2 * g + 1][0], bf[2 * g + 1][1], addr);
            }
#pragma unroll
            for (int mt = 0; mt < 4; mt++)
#pragma unroll
                for (int nf = 0; nf < 4; nf++) mma_f16(acc[mt][nf], af[mt], bf[nf]);
        }
        __syncthreads();
    }
#undef G_LOAD_STAGE

#pragma unroll
    for (int mt = 0; mt < 4; mt++) {
        int row0 = m0 + wm * 64 + mt * 16 + r;
#pragma unroll
        for (int nf = 0; nf < 4; nf++) {
            int col = n0 + wn * 32 + nf * 8 + 2 * cq;
            store_pair(C + (size_t)row0 * N + col, acc[mt][nf][0], acc[mt][nf][1]);
            store_pair(C + (size_t)(row0 + 8) * N + col, acc[mt][nf][2], acc[mt][nf][3]);
        }
    }
}

__global__ __launch_bounds__(GTHREADS, 2) void gemm_qkv_kernel(
    const __half* __restrict__ x,
    const __half* __restrict__ wq, const __half* __restrict__ wk, const __half* __restrict__ wv,
    __half* __restrict__ q, __half* __restrict__ k, __half* __restrict__ v) {
    extern __shared__ char smem[];
    const __half* B = (blockIdx.z == 0) ? wq : (blockIdx.z == 1) ? wk : wv;
    __half* C       = (blockIdx.z == 0) ? q  : (blockIdx.z == 1) ? k  : v;
    gemm_fp16_body<__half>(x, B, C, smem);
}

__global__ __launch_bounds__(GTHREADS, 2) void gemm_out_kernel(const __half* __restrict__ A,
                                                               const __half* __restrict__ B,
                                                               float* __restrict__ C) {
    extern __shared__ char smem[];
    gemm_fp16_body<float>(A, B, C, smem);
}

// ---------------------------------------------------------------------------
// RoPE (non-interleaved / chunk-half), in-place on fp16 Q and K.
// ---------------------------------------------------------------------------
__global__ void rope_kernel(__half* __restrict__ q, __half* __restrict__ k) {
    int t = blockIdx.x * blockDim.x + threadIdx.x;
    const int total = BATCH * SEQ * NHEAD * 64;
    if (t >= total) return;
    int j = t & 63;
    int h = (t >> 6) & (NHEAD - 1);
    int s = (t >> 10) & (SEQ - 1);
    int b = t >> 21;
    size_t off = ((size_t)(b * SEQ + s)) * DIM + h * HDIM + j;
    float inv = powf(10000.0f, -(float)(2 * j) * (1.0f / 128.0f));
    float ph = (float)s * inv;
    float sn, cs;
    sincosf(ph, &sn, &cs);
    float q1 = __half2float(q[off]), q2 = __half2float(q[off + 64]);
    q[off]      = __float2half_rn(q1 * cs - q2 * sn);
    q[off + 64] = __float2half_rn(q1 * sn + q2 * cs);
    float k1 = __half2float(k[off]), k2 = __half2float(k[off + 64]);
    k[off]      = __float2half_rn(k1 * cs - k2 * sn);
    k[off + 64] = __float2half_rn(k1 * sn + k2 * cs);
}

// ---------------------------------------------------------------------------
// Causal flash attention, fp16 mma. Grid: (S/64, H, B), 128 threads
// (4 warps x 16 q-rows). 32-key blocks. Q in registers; K via ldmatrix,
// V via ldmatrix.trans (no transpose-on-store); P-fragments packed directly
// from S accumulators (no smem staging).
// ---------------------------------------------------------------------------
#define KPAD 136   // padded row stride in halfs (272 B) — conflict-free ldmatrix

__global__ __launch_bounds__(128) void flash_kernel(const __half* __restrict__ Q,
                                                    const __half* __restrict__ Kg,
                                                    const __half* __restrict__ Vg,
                                                    __half* __restrict__ O) {
    __shared__ __half Ks[32][KPAD];
    __shared__ __half Vs[32][KPAD];

    const int tid = threadIdx.x;
    const int warp = tid >> 5, lane = tid & 31;
    const int r = lane >> 2, cq = lane & 3;
    const int q0 = blockIdx.x * 64;
    const int h = blockIdx.y, b = blockIdx.z;
    const size_t head_off = (size_t)b * SEQ * DIM + (size_t)h * HDIM;
    const uint32_t uK = smem_u32(&Ks[0][0]);
    const uint32_t uV = smem_u32(&Vs[0][0]);

    // ---- Q fragments: 8 k16-chunks x 4 regs ----
    const __half* Qp = Q + head_off + (size_t)(q0 + warp * 16) * DIM;
    uint32_t aQ[8][4];
#pragma unroll
    for (int kc = 0; kc < 8; kc++) {
        aQ[kc][0] = *(const uint32_t*)(Qp + (size_t)r * DIM + kc * 16 + 2 * cq);
        aQ[kc][1] = *(const uint32_t*)(Qp + (size_t)(r + 8) * DIM + kc * 16 + 2 * cq);
        aQ[kc][2] = *(const uint32_t*)(Qp + (size_t)r * DIM + kc * 16 + 8 + 2 * cq);
        aQ[kc][3] = *(const uint32_t*)(Qp + (size_t)(r + 8) * DIM + kc * 16 + 8 + 2 * cq);
    }

    float o[16][4];
#pragma unroll
    for (int i = 0; i < 16; i++)
#pragma unroll
        for (int j = 0; j < 4; j++) o[i][j] = 0.f;
    float m0 = -1e30f, m1 = -1e30f, l0 = 0.f, l1 = 0.f;

    const int nkb = (q0 >> 5) + 2;
    for (int kb = 0; kb < nkb; kb++) {
        const int kstart = kb * 32;
        __syncthreads();

        // K,V tiles -> smem (uint4, coalesced; 512 chunks each, 4/thread)
        const __half* Kp = Kg + head_off + (size_t)kstart * DIM;
        const __half* Vp = Vg + head_off + (size_t)kstart * DIM;
#pragma unroll
        for (int i = 0; i < 4; i++) {
            int c = tid + i * 128;
            int row = c >> 4, ch = c & 15;
            *(uint4*)&Ks[row][ch * 8] = *(const uint4*)(Kp + (size_t)row * DIM + ch * 8);
            *(uint4*)&Vs[row][ch * 8] = *(const uint4*)(Vp + (size_t)row * DIM + ch * 8);
        }
        __syncthreads();

        // ---- S = Q K^T (16 rows x 32 keys per warp) ----
        float s[4][4];
#pragma unroll
        for (int nt = 0; nt < 4; nt++)
#pragma unroll
            for (int j = 0; j < 4; j++) s[nt][j] = 0.f;
#pragma unroll
        for (int kc = 0; kc < 8; kc++) {
            uint32_t bf[4][2];
#pragma unroll
            for (int g = 0; g < 2; g++) {
                int row = g * 16 + (lane & 7) + ((lane >> 4) << 3);
                int ch = kc * 2 + ((lane >> 3) & 1);
                uint32_t addr = uK + (uint32_t)(row * (KPAD * 2) + ch * 16);
                LDSM_X4(bf[2 * g][0], bf[2 * g][1], bf[2 * g + 1][0], bf[2 * g + 1][1], addr);
            }
#pragma unroll
            for (int nt = 0; nt < 4; nt++) mma_f16(s[nt], aQ[kc], bf[nt]);
        }

        const float scale = 0.08838834764831843f;  // 1/sqrt(128)
        const int qrow0 = q0 + warp * 16 + r;
        const bool need_mask = (kstart + 31 > q0 + warp * 16);
#pragma unroll
        for (int nt = 0; nt < 4; nt++) {
#pragma unroll
            for (int u = 0; u < 2; u++) {
                int key = kstart + nt * 8 + 2 * cq + u;
                s[nt][u] *= scale;
                s[nt][2 + u] *= scale;
                if (need_mask) {
                    if (key > qrow0) s[nt][u] = -1e30f;
                    if (key > qrow0 + 8) s[nt][2 + u] = -1e30f;
                }
            }
        }

        // ---- online softmax ----
        float mx0 = -1e30f, mx1 = -1e30f;
#pragma unroll
        for (int nt = 0; nt < 4; nt++) {
            mx0 = fmaxf(mx0, fmaxf(s[nt][0], s[nt][1]));
            mx1 = fmaxf(mx1, fmaxf(s[nt][2], s[nt][3]));
        }
        mx0 = fmaxf(mx0, __shfl_xor_sync(0xffffffffu, mx0, 1));
        mx0 = fmaxf(mx0, __shfl_xor_sync(0xffffffffu, mx0, 2));
        mx1 = fmaxf(mx1, __shfl_xor_sync(0xffffffffu, mx1, 1));
        mx1 = fmaxf(mx1, __shfl_xor_sync(0xffffffffu, mx1, 2));
        float mn0 = fmaxf(m0, mx0), mn1 = fmaxf(m1, mx1);
        float al0 = __expf(m0 - mn0), al1 = __expf(m1 - mn1);
        float sum0 = 0.f, sum1 = 0.f;
#pragma unroll
        for (int nt = 0; nt < 4; nt++) {
            s[nt][0] = __expf(s[nt][0] - mn0);
            s[nt][1] = __expf(s[nt][1] - mn0);
            s[nt][2] = __expf(s[nt][2] - mn1);
            s[nt][3] = __expf(s[nt][3] - mn1);
            sum0 += s[nt][0] + s[nt][1];
            sum1 += s[nt][2] + s[nt][3];
        }
        sum0 += __shfl_xor_sync(0xffffffffu, sum0, 1);
        sum0 += __shfl_xor_sync(0xffffffffu, sum0, 2);
        sum1 += __shfl_xor_sync(0xffffffffu, sum1, 1);
        sum1 += __shfl_xor_sync(0xffffffffu, sum1, 2);
        l0 = l0 * al0 + sum0;
        l1 = l1 * al1 + sum1;
        m0 = mn0;
        m1 = mn1;
#pragma unroll
        for (int nt = 0; nt < 16; nt++) {
            o[nt][0] *= al0;
            o[nt][1] *= al0;
            o[nt][2] *= al1;
            o[nt][3] *= al1;
        }

        // ---- O += P V : P fragments packed straight from S accumulators ----
#pragma unroll
        for (int g = 0; g < 2; g++) {
            uint32_t aP[4];
            aP[0] = packh2(s[2 * g][0], s[2 * g][1]);
            aP[1] = packh2(s[2 * g][2], s[2 * g][3]);
            aP[2] = packh2(s[2 * g + 1][0], s[2 * g + 1][1]);
            aP[3] = packh2(s[2 * g + 1][2], s[2 * g + 1][3]);
#pragma unroll
            for (int p = 0; p < 8; p++) {   // pairs of d-tiles
                uint32_t bv[2][2];
                int row = g * 16 + (lane & 7) + (((lane >> 3) & 1) << 3);
                int ch = 2 * p + (lane >> 4);
                uint32_t addr = uV + (uint32_t)(row * (KPAD * 2) + ch * 16);
                LDSM_X4_T(bv[0][0], bv[0][1], bv[1][0], bv[1][1], addr);
                mma_f16(o[2 * p], aP, bv[0]);
                mma_f16(o[2 * p + 1], aP, bv[1]);
            }
        }
    }

    const float inv0 = 1.f / l0, inv1 = 1.f / l1;
    __half* Op = O + head_off + (size_t)(q0 + warp * 16) * DIM;
#pragma unroll
    for (int nt = 0; nt < 16; nt++) {
        int col = nt * 8 + 2 * cq;
        store_pair(Op + (size_t)r * DIM + col, o[nt][0] * inv0, o[nt][1] * inv0);
        store_pair(Op + (size_t)(r + 8) * DIM + col, o[nt][2] * inv1, o[nt][3] * inv1);
    }
}

// ---------------------------------------------------------------------------
extern "C" void kernel_launch(void* const* d_in, const int* in_sizes, int n_in,
                              void* d_out, int out_size) {
    const float* x  = (const float*)d_in[0];
    const float* Wq = (const float*)d_in[1];
    const float* Wk = (const float*)d_in[2];
    const float* Wv = (const float*)d_in[3];
    const float* Wo = (const float*)d_in[4];
    float* out = (float*)d_out;

    __half *qp, *kp, *vp, *ap, *xr, *wqr, *wkr, *wvr, *wor;
    cudaGetSymbolAddress((void**)&qp, g_q);
    cudaGetSymbolAddress((void**)&kp, g_k);
    cudaGetSymbolAddress((void**)&vp, g_v);
    cudaGetSymbolAddress((void**)&ap, g_attn);
    cudaGetSymbolAddress((void**)&xr, g_xr);
    cudaGetSymbolAddress((void**)&wqr, g_wqr);
    cudaGetSymbolAddress((void**)&wkr, g_wkr);
    cudaGetSymbolAddress((void**)&wvr, g_wvr);
    cudaGetSymbolAddress((void**)&wor, g_wor);

    cudaFuncSetAttribute(gemm_qkv_kernel, cudaFuncAttributeMaxDynamicSharedMemorySize, GSMEM_BYTES);
    cudaFuncSetAttribute(gemm_out_kernel, cudaFuncAttributeMaxDynamicSharedMemorySize, GSMEM_BYTES);

    const int nx4 = MROWS * DIM / 4;
    const int nw4 = DIM * DIM / 4;
    f32_to_f16_kernel<<<(nx4 + 255) / 256, 256>>>(x, xr, nx4);
    f32_to_f16_kernel<<<(nw4 + 255) / 256, 256>>>(Wq, wqr, nw4);
    f32_to_f16_kernel<<<(nw4 + 255) / 256, 256>>>(Wk, wkr, nw4);
    f32_to_f16_kernel<<<(nw4 + 255) / 256, 256>>>(Wv, wvr, nw4);
    f32_to_f16_kernel<<<(nw4 + 255) / 256, 256>>>(Wo, wor, nw4);

    dim3 gqkv(DIM / GBN, MROWS / GBM, 3);  // (16, 32, 3)
    gemm_qkv_kernel<<<gqkv, GTHREADS, GSMEM_BYTES>>>(xr, wqr, wkr, wvr, qp, kp, vp);

    const int rope_threads = BATCH * SEQ * NHEAD * 64;
    rope_kernel<<<rope_threads / 256, 256>>>(qp, kp);

    flash_kernel<<<dim3(SEQ / 64, NHEAD, BATCH), 128>>>(qp, kp, vp, ap);

    gemm_out_kernel<<<dim3(DIM / GBN, MROWS / GBM), GTHREADS, GSMEM_BYTES>>>(ap, wor, out);
}